// round 1
// baseline (speedup 1.0000x reference)
#include <cuda_runtime.h>
#include <cstdint>
#include <cstddef>

#define NN 100000
#define DD 128
#define AA 3
#define PP 50000
#define EE 500000
#define EFN 500000

#define ND  ((size_t)NN * DD)      // 12,800,000
#define AND ((size_t)AA * NN * DD) // 38,400,000
#define PD  ((size_t)PP * DD)      // 6,400,000

// ---------------- scratch (static device globals; no allocation) ----------------
__device__ float  g_xatt_a[AA * NN * DD];
__device__ float  g_xatt_b[AA * NN * DD];
__device__ float  g_agg   [AA * NN * DD];
__device__ float  g_agg3  [NN * DD];
__device__ float  g_cnt   [AA * NN];
__device__ float  g_cnt3  [NN];
__device__ float  g_esf   [AA * PP * DD];
__device__ float  g_wt    [262144];          // transposed weights, [i][o] layout
__device__ double g_inv   [AA * 128 * 256];  // Gauss-Jordan scratch
__device__ float  g_M     [AA * 128 * 128];  // inv(proj)+I, [i][o]

// transposed-weight offsets
#define WT_AGG1 0
#define WT_AGG2 16384
#define WT_L1   32768
#define WT_R1   81920
#define WT_L2   131072
#define WT_R2   180224
#define WT_L3   229376
#define WT_R3   245760

// ---------------- weight transpose: dst[b][i][o] = src[b*bstride + o*ld + i] ----
__global__ void transpose_wt(float* __restrict__ dst, const float* __restrict__ src,
                             int ldsrc, long bstride) {
    int b = blockIdx.x;
    const float* s = src + (size_t)b * bstride;
    float* d = dst + (size_t)b * 16384;
    for (int idx = threadIdx.x; idx < 16384; idx += blockDim.x) {
        int i = idx >> 7, o = idx & 127;
        d[idx] = s[(size_t)o * ldsrc + i];
    }
}

// ---------------- fp64 Gauss-Jordan with partial pivoting; M = inv(proj)+I -----
__global__ void inv_kernel(const float* __restrict__ proj) {
    int a = blockIdx.x;
    double* A = g_inv + (size_t)a * 128 * 256;
    int tid = threadIdx.x;  // 256 threads

    for (int idx = tid; idx < 128 * 256; idx += 256) {
        int r = idx >> 8, c = idx & 255;
        A[idx] = (c < 128) ? (double)proj[(size_t)a * 16384 + r * 128 + c]
                           : ((c - 128) == r ? 1.0 : 0.0);
    }
    __syncthreads();

    __shared__ double pv[128];
    __shared__ int    pi[128];
    for (int k = 0; k < 128; k++) {
        if (tid < 128) {
            pv[tid] = (tid >= k) ? fabs(A[(size_t)tid * 256 + k]) : -1.0;
            pi[tid] = tid;
        }
        __syncthreads();
        for (int s = 64; s > 0; s >>= 1) {
            if (tid < s && pv[tid + s] > pv[tid]) { pv[tid] = pv[tid + s]; pi[tid] = pi[tid + s]; }
            __syncthreads();
        }
        int piv = pi[0];
        if (piv != k && tid < 256) {
            // swap rows k and piv (each thread owns one column)
            double t = A[(size_t)k * 256 + tid];
            A[(size_t)k * 256 + tid] = A[(size_t)piv * 256 + tid];
            A[(size_t)piv * 256 + tid] = t;
        }
        __syncthreads();
        double pinv = 1.0 / A[(size_t)k * 256 + k];
        A[(size_t)k * 256 + tid] *= pinv;
        __syncthreads();
        int r = tid >> 1, h = tid & 1;
        double f = (r != k) ? A[(size_t)r * 256 + k] : 0.0;
        __syncthreads();
        if (r != k) {
            int j0 = h * 128;
            #pragma unroll 4
            for (int j = j0; j < j0 + 128; j++)
                A[(size_t)r * 256 + j] -= f * A[(size_t)k * 256 + j];
        }
        __syncthreads();
    }
    for (int idx = tid; idx < 16384; idx += 256) {
        int i = idx >> 7, o = idx & 127;
        g_M[(size_t)a * 16384 + idx] =
            (float)(A[(size_t)i * 256 + 128 + o] + (i == o ? 1.0 : 0.0));
    }
}

// ---------------- edge scatter: agg[si[e]] += data[gi[e]]; cnt[si[e]] += 1 ------
__global__ void scatter_add(const float* __restrict__ data,
                            const int* __restrict__ gi,
                            const int* __restrict__ si,
                            float* __restrict__ agg,
                            float* __restrict__ cnt, int ne) {
    int t = blockIdx.x * blockDim.x + threadIdx.x;
    int w = t >> 5, lane = t & 31;
    if (w >= ne) return;
    int g = gi[w], s = si[w];
    float4 v = ((const float4*)(data + (size_t)g * DD))[lane];
    float* dp = agg + (size_t)s * DD + lane * 4;
    atomicAdd(dp + 0, v.x);
    atomicAdd(dp + 1, v.y);
    atomicAdd(dp + 2, v.z);
    atomicAdd(dp + 3, v.w);
    if (lane == 0) atomicAdd(cnt + s, 1.0f);
}

// ---------------- fused GEMM ----------------------------------------------------
// Out[row] = act( scale(row)*In1[row] @ Wt1 + In2[row] @ Wt2 + bias )
// Wt layout: [i][o] (pre-transposed). Block = 128 rows x full 128 cols, BK=16.
// GATHER: In1 and Out rows are ridx[row]; In2 always linear. In-place safe
// (each block reads its full rows before writing them).
template<bool HAS2, bool GATHER, bool HASCNT, bool RELU, bool HASBIAS>
__global__ __launch_bounds__(256, 2)
void gemm128(const float* __restrict__ In1, int in1Stride,
             const float* __restrict__ Wt1,
             const float* __restrict__ In2,
             const float* __restrict__ Wt2,
             const float* __restrict__ bias,
             const float* __restrict__ cnt,
             const int*   __restrict__ ridx,
             float* __restrict__ Out,
             int nrows) {
    __shared__ float sA1[16][132];
    __shared__ float sA2[16][132];
    __shared__ float sW1[16][128];
    __shared__ float sW2[16][128];
    __shared__ int   sRow[128];
    __shared__ float sScale[128];

    int tid = threadIdx.x;
    int row0 = blockIdx.x * 128;

    if (tid < 128) {
        int g = row0 + tid;
        int e = 0; float sc = 0.0f;
        if (g < nrows) {
            e = GATHER ? ridx[g] : g;
            sc = 1.0f;
            if (HASCNT) sc = 1.0f / fmaxf(cnt[e], 1.0f);
        }
        sRow[tid] = e;
        sScale[tid] = sc;
    }
    __syncthreads();

    float acc[8][8];
    #pragma unroll
    for (int r = 0; r < 8; r++)
        #pragma unroll
        for (int c = 0; c < 8; c++) acc[r][c] = 0.0f;

    int tx = tid & 15, ty = tid >> 4;

    for (int kt = 0; kt < 8; kt++) {
        int k0 = kt * 16;
        #pragma unroll
        for (int q = 0; q < 2; q++) {
            int f = tid * 2 + q;            // 0..511
            int row = f >> 2, cs = f & 3;   // 128 rows x 4 float4 segments
            int e = sRow[row];
            float sc = sScale[row];
            float4 v = *(const float4*)(In1 + (size_t)e * in1Stride + k0 + cs * 4);
            sA1[cs * 4 + 0][row] = v.x * sc;
            sA1[cs * 4 + 1][row] = v.y * sc;
            sA1[cs * 4 + 2][row] = v.z * sc;
            sA1[cs * 4 + 3][row] = v.w * sc;
            if (HAS2) {
                int g2 = row0 + row; if (g2 >= nrows) g2 = 0;
                float4 u = *(const float4*)(In2 + (size_t)g2 * DD + k0 + cs * 4);
                sA2[cs * 4 + 0][row] = u.x;
                sA2[cs * 4 + 1][row] = u.y;
                sA2[cs * 4 + 2][row] = u.z;
                sA2[cs * 4 + 3][row] = u.w;
            }
            int wr = f >> 5, wc = f & 31;   // 16 k-rows x 32 float4
            *(float4*)&sW1[wr][wc * 4] = *(const float4*)(Wt1 + (size_t)(k0 + wr) * 128 + wc * 4);
            if (HAS2)
                *(float4*)&sW2[wr][wc * 4] = *(const float4*)(Wt2 + (size_t)(k0 + wr) * 128 + wc * 4);
        }
        __syncthreads();

        #pragma unroll
        for (int k = 0; k < 16; k++) {
            float4 wa = *(float4*)&sW1[k][tx * 8];
            float4 wb = *(float4*)&sW1[k][tx * 8 + 4];
            float4 ia = *(float4*)&sA1[k][ty * 8];
            float4 ib = *(float4*)&sA1[k][ty * 8 + 4];
            float wv[8] = {wa.x, wa.y, wa.z, wa.w, wb.x, wb.y, wb.z, wb.w};
            float iv[8] = {ia.x, ia.y, ia.z, ia.w, ib.x, ib.y, ib.z, ib.w};
            #pragma unroll
            for (int r = 0; r < 8; r++)
                #pragma unroll
                for (int c = 0; c < 8; c++) acc[r][c] += iv[r] * wv[c];
            if (HAS2) {
                float4 wa2 = *(float4*)&sW2[k][tx * 8];
                float4 wb2 = *(float4*)&sW2[k][tx * 8 + 4];
                float4 ia2 = *(float4*)&sA2[k][ty * 8];
                float4 ib2 = *(float4*)&sA2[k][ty * 8 + 4];
                float wv2[8] = {wa2.x, wa2.y, wa2.z, wa2.w, wb2.x, wb2.y, wb2.z, wb2.w};
                float iv2[8] = {ia2.x, ia2.y, ia2.z, ia2.w, ib2.x, ib2.y, ib2.z, ib2.w};
                #pragma unroll
                for (int r = 0; r < 8; r++)
                    #pragma unroll
                    for (int c = 0; c < 8; c++) acc[r][c] += iv2[r] * wv2[c];
            }
        }
        __syncthreads();
    }

    float bv[8];
    #pragma unroll
    for (int c = 0; c < 8; c++) bv[c] = HASBIAS ? bias[tx * 8 + c] : 0.0f;

    #pragma unroll
    for (int r = 0; r < 8; r++) {
        int lr = ty * 8 + r;
        int g = row0 + lr;
        if (g < nrows) {
            int orow = GATHER ? sRow[lr] : g;
            float* op = Out + (size_t)orow * DD + tx * 8;
            float v[8];
            #pragma unroll
            for (int c = 0; c < 8; c++) {
                float x = acc[r][c] + bv[c];
                if (RELU) x = fmaxf(x, 0.0f);
                v[c] = x;
            }
            *(float4*)op       = make_float4(v[0], v[1], v[2], v[3]);
            *((float4*)op + 1) = make_float4(v[4], v[5], v[6], v[7]);
        }
    }
}

// ---------------- host orchestration -------------------------------------------
extern "C" void kernel_launch(void* const* d_in, const int* in_sizes, int n_in,
                              void* d_out, int out_size) {
    // Resolve input ordering: dict order has in_sizes[3]==P (population);
    // signature order has in_sizes[3]==A*D*D (proj).
    int iXI, iXA, iPF, iPOP, iEIA, iEIF, iPROJ, iAGGW, iAGGB,
        iWL1, iBL1, iWR1, iWL2, iBL2, iWR2, iWL3, iBL3, iWR3;
    if (in_sizes[3] == PP) {  // setup_inputs dict order
        iXI = 0; iXA = 1; iPF = 2; iPOP = 3; iEIA = 4; iEIF = 5;
        iPROJ = 6; iAGGW = 7; iAGGB = 8; iWL1 = 9; iBL1 = 10; iWR1 = 11;
        iWL2 = 12; iBL2 = 13; iWR2 = 14; iWL3 = 15; iBL3 = 16; iWR3 = 17;
    } else {                  // reference() signature order
        iXI = 0; iXA = 1; iPF = 2; iPROJ = 3; iAGGW = 4; iAGGB = 5;
        iWL1 = 6; iBL1 = 7; iWR1 = 8; iWL2 = 9; iBL2 = 10; iWR2 = 11;
        iWL3 = 12; iBL3 = 13; iWR3 = 14; iPOP = 15; iEIA = 16; iEIF = 17;
    }

    const float* xi   = (const float*)d_in[iXI];
    const float* xa   = (const float*)d_in[iXA];
    const float* pf   = (const float*)d_in[iPF];
    const int*   pop  = (const int*)d_in[iPOP];
    const int*   eia  = (const int*)d_in[iEIA];
    const int*   eif  = (const int*)d_in[iEIF];
    const float* proj = (const float*)d_in[iPROJ];
    const float* aggW = (const float*)d_in[iAGGW];
    const float* aggB = (const float*)d_in[iAGGB];
    const float* wl1  = (const float*)d_in[iWL1];
    const float* bl1  = (const float*)d_in[iBL1];
    const float* wr1  = (const float*)d_in[iWR1];
    const float* wl2  = (const float*)d_in[iWL2];
    const float* bl2  = (const float*)d_in[iBL2];
    const float* wr2  = (const float*)d_in[iWR2];
    const float* wl3  = (const float*)d_in[iWL3];
    const float* bl3  = (const float*)d_in[iBL3];
    const float* wr3  = (const float*)d_in[iWR3];

    float* out = (float*)d_out;            // [x_ind_out (N*D)] then [x_att_out (A*N*D)]

    float *xatt_a, *xatt_b, *agg, *agg3, *cnt, *cnt3, *esf, *wt, *Mbuf;
    cudaGetSymbolAddress((void**)&xatt_a, g_xatt_a);
    cudaGetSymbolAddress((void**)&xatt_b, g_xatt_b);
    cudaGetSymbolAddress((void**)&agg,    g_agg);
    cudaGetSymbolAddress((void**)&agg3,   g_agg3);
    cudaGetSymbolAddress((void**)&cnt,    g_cnt);
    cudaGetSymbolAddress((void**)&cnt3,   g_cnt3);
    cudaGetSymbolAddress((void**)&esf,    g_esf);
    cudaGetSymbolAddress((void**)&wt,     g_wt);
    cudaGetSymbolAddress((void**)&Mbuf,   g_M);

    const int gP = (PP + 127) / 128;  // 391
    const int gN = (NN + 127) / 128;  // 782
    const int sB = (EE + 7) / 8;      // scatter blocks (32 lanes/edge, 256 thr)
    const int sB3 = (EFN + 7) / 8;

    // 0) transposed weights ([i][o] layout)
    transpose_wt<<<1, 256>>>(wt + WT_AGG1, aggW,        256, 0);
    transpose_wt<<<1, 256>>>(wt + WT_AGG2, aggW + 128,  256, 0);
    transpose_wt<<<AA, 256>>>(wt + WT_L1,  wl1, 128, 16384);
    transpose_wt<<<AA, 256>>>(wt + WT_R1,  wr1, 128, 16384);
    transpose_wt<<<AA, 256>>>(wt + WT_L2,  wl2, 128, 16384);
    transpose_wt<<<AA, 256>>>(wt + WT_R2,  wr2, 128, 16384);
    transpose_wt<<<1, 256>>>(wt + WT_L3,   wl3, 128, 0);
    transpose_wt<<<1, 256>>>(wt + WT_R3,   wr3, 128, 0);

    // 1) M = inv(proj) + I   (fp64 Gauss-Jordan, one block per attribute)
    inv_kernel<<<AA, 256>>>(proj);

    // 2) zero accumulators
    cudaMemsetAsync(agg,  0, AND * sizeof(float), 0);
    cudaMemsetAsync(cnt,  0, (size_t)AA * NN * sizeof(float), 0);
    cudaMemsetAsync(agg3, 0, ND * sizeof(float), 0);
    cudaMemsetAsync(cnt3, 0, (size_t)NN * sizeof(float), 0);

    // 3) esf[a] = PF[:,a,:] @ proj[a]    (proj already [i][o])
    for (int a = 0; a < AA; a++)
        gemm128<false, false, false, false, false><<<gP, 256>>>(
            pf + a * DD, AA * DD, proj + (size_t)a * 16384,
            nullptr, nullptr, nullptr, nullptr, nullptr,
            esf + (size_t)a * PD, PP);

    // 4) x_att_a = x_attributes (copy), then overwrite population rows with h
    cudaMemcpyAsync(xatt_a, xa, AND * sizeof(float), cudaMemcpyDeviceToDevice, 0);
    for (int a = 0; a < AA; a++)
        gemm128<true, true, false, true, true><<<gP, 256>>>(
            xa + (size_t)a * ND, DD, wt + WT_AGG1,
            esf + (size_t)a * PD, wt + WT_AGG2,
            aggB, nullptr, pop,
            xatt_a + (size_t)a * ND, PP);

    // 5) agg1: segment-sum of x_individuals[src] over dst
    for (int a = 0; a < AA; a++)
        scatter_add<<<sB, 256>>>(xi,
            eia + (size_t)a * 2 * EE,            // src (gather)
            eia + (size_t)a * 2 * EE + EE,       // dst (segment)
            agg + (size_t)a * ND, cnt + (size_t)a * NN, EE);

    // 6) x_att_b = mean(agg1) @ W_l1^T + b_l1 + x_att_a @ W_r1^T
    for (int a = 0; a < AA; a++)
        gemm128<true, false, true, false, true><<<gN, 256>>>(
            agg + (size_t)a * ND, DD, wt + WT_L1 + (size_t)a * 16384,
            xatt_a + (size_t)a * ND, wt + WT_R1 + (size_t)a * 16384,
            bl1 + a * DD, cnt + (size_t)a * NN, nullptr,
            xatt_b + (size_t)a * ND, NN);

    // 7) population rows: x_att_b[pop] = relu(x_att_b[pop] @ M[a])   (in-place safe)
    for (int a = 0; a < AA; a++)
        gemm128<false, true, false, true, false><<<gP, 256>>>(
            xatt_b + (size_t)a * ND, DD, Mbuf + (size_t)a * 16384,
            nullptr, nullptr, nullptr, nullptr, pop,
            xatt_b + (size_t)a * ND, PP);

    // 8) agg2: segment-sum of x_att_b[dst] over src
    cudaMemsetAsync(agg, 0, AND * sizeof(float), 0);
    cudaMemsetAsync(cnt, 0, (size_t)AA * NN * sizeof(float), 0);
    for (int a = 0; a < AA; a++)
        scatter_add<<<sB, 256>>>(xatt_b + (size_t)a * ND,
            eia + (size_t)a * 2 * EE + EE,       // dst (gather)
            eia + (size_t)a * 2 * EE,            // src (segment)
            agg + (size_t)a * ND, cnt + (size_t)a * NN, EE);

    // 9) x_att_out = mean(agg2) @ W_l2^T + b_l2 + x_att_b @ W_r2^T  -> d_out[N*D:]
    for (int a = 0; a < AA; a++)
        gemm128<true, false, true, false, true><<<gN, 256>>>(
            agg + (size_t)a * ND, DD, wt + WT_L2 + (size_t)a * 16384,
            xatt_b + (size_t)a * ND, wt + WT_R2 + (size_t)a * 16384,
            bl2 + a * DD, cnt + (size_t)a * NN, nullptr,
            out + ND + (size_t)a * ND, NN);

    // 10) agg3: family segment-mean of x_individuals[eif[1]] over eif[0]
    scatter_add<<<sB3, 256>>>(xi, eif + EFN, eif, agg3, cnt3, EFN);

    // 11) x_ind_out = mean(agg3) @ W_l3^T + b_l3 + x_individuals @ W_r3^T -> d_out[0:]
    gemm128<true, false, true, false, true><<<gN, 256>>>(
        agg3, DD, wt + WT_L3,
        xi, wt + WT_R3,
        bl3, cnt3, nullptr,
        out, NN);
}